// round 2
// baseline (speedup 1.0000x reference)
#include <cuda_runtime.h>
#include <cstdint>

#define V_NODES   1000000
#define N_GRAPHS  50000
#define NODE_DIM  128
#define HIDDEN    128
#define GDIM      64

// ---------------- scratch (no allocation allowed) ----------------
__device__ __align__(256) float g_Z1[(size_t)N_GRAPHS * HIDDEN];   // segment sums
__device__ __align__(256) float g_cnt[N_GRAPHS];                   // segment counts
__device__ int   g_is64;                                           // node2graph dtype flag

// ---------------- helpers ----------------
__device__ __forceinline__ unsigned f2tf(float f) {
    unsigned u;
    asm("cvt.rna.tf32.f32 %0, %1;" : "=r"(u) : "f"(f));
    return u;
}

__device__ __forceinline__ void mma_tf32(float& c0, float& c1, float& c2, float& c3,
                                         unsigned a0, unsigned a1, unsigned a2, unsigned a3,
                                         unsigned b0, unsigned b1) {
    asm volatile(
        "mma.sync.aligned.m16n8k8.row.col.f32.tf32.tf32.f32 "
        "{%0,%1,%2,%3},{%4,%5,%6,%7},{%8,%9},{%0,%1,%2,%3};"
        : "+f"(c0), "+f"(c1), "+f"(c2), "+f"(c3)
        : "r"(a0), "r"(a1), "r"(a2), "r"(a3), "r"(b0), "r"(b1));
}

__device__ __forceinline__ void red4(float* p, float4 v) {
    asm volatile("red.global.add.v4.f32 [%0], {%1,%2,%3,%4};"
                 :: "l"(p), "f"(v.x), "f"(v.y), "f"(v.z), "f"(v.w) : "memory");
}

__device__ __forceinline__ float sigm(float x) { return 1.0f / (1.0f + __expf(-x)); }

// ---------------- kernel 0: zero scratch ----------------
__global__ void k_zero() {
    size_t i = (size_t)blockIdx.x * blockDim.x + threadIdx.x;
    size_t stride = (size_t)gridDim.x * blockDim.x;
    float4* z = reinterpret_cast<float4*>(g_Z1);
    const size_t n4 = (size_t)N_GRAPHS * HIDDEN / 4;
    for (size_t k = i; k < n4; k += stride) z[k] = make_float4(0.f, 0.f, 0.f, 0.f);
    for (size_t k = i; k < N_GRAPHS; k += stride) g_cnt[k] = 0.f;
}

// ---------------- kernel 1: detect int64 vs int32 node2graph ----------------
// If stored as little-endian int64 (values < 2^31), every odd 32-bit word is 0.
// If int32, odd words are random graph ids in [0, 50000) -> almost surely nonzero.
__global__ void k_detect(const unsigned* __restrict__ n2g_words) {
    __shared__ int nz;
    if (threadIdx.x == 0) nz = 0;
    __syncthreads();
    unsigned w = n2g_words[2 * threadIdx.x + 1];   // idx <= 2047, safe for both layouts
    if (w != 0u) atomicOr(&nz, 1);
    __syncthreads();
    if (threadIdx.x == 0) g_is64 = (nz == 0) ? 1 : 0;
}

// ---------------- kernel 2: node MLP (gated) + segment scatter ----------------
// Tile: 128 nodes/block, N = 256 (W1,W2 rows interleaved: row 2j=W1[j], 2j+1=W2[j]),
// K = 128 in 4 chunks of 32. 512 threads = 16 warps, 4(m) x 4(n) warp grid,
// warp tile 32(m) x 64(n). TF32 m16n8k8 mma.sync.
#define SM_XS    0                    // 128 x 36 floats
#define SM_WS    (128*36)             // 256 x 36 floats
#define SM_HS    (SM_WS + 256*36)     // 128 x 132 floats
#define SM_B1    (SM_HS + 128*132)    // 128
#define SM_B2    (SM_B1 + 128)        // 128
#define SM_GID   (SM_B2 + 128)        // 128 ints
#define SMEM_NODES_BYTES ((SM_GID + 128) * 4)

__global__ __launch_bounds__(512, 1)
void k_nodes(const float* __restrict__ x, const void* __restrict__ n2g,
             const float* __restrict__ W1, const float* __restrict__ b1,
             const float* __restrict__ W2, const float* __restrict__ b2) {
    extern __shared__ float smem[];
    float* XS = smem + SM_XS;
    float* WS = smem + SM_WS;
    float* HS = smem + SM_HS;
    float* B1S = smem + SM_B1;
    float* B2S = smem + SM_B2;
    int*   GID = reinterpret_cast<int*>(smem + SM_GID);

    const int tid = threadIdx.x;
    const int lane = tid & 31;
    const int wid = tid >> 5;
    const int wm = wid >> 2;          // 0..3 -> m base = wm*32
    const int wn = wid & 3;           // 0..3 -> n base = wn*64
    const int node0 = blockIdx.x * 128;
    const int is64 = g_is64;

    if (tid < 128)       B1S[tid]       = b1[tid];
    else if (tid < 256)  B2S[tid - 128] = b2[tid - 128];

    float c[2][8][4];
    #pragma unroll
    for (int mi = 0; mi < 2; ++mi)
        #pragma unroll
        for (int ni = 0; ni < 8; ++ni)
            #pragma unroll
            for (int q = 0; q < 4; ++q) c[mi][ni][q] = 0.f;

    for (int kc = 0; kc < 4; ++kc) {
        __syncthreads();
        // stage X chunk [128][32] -> tf32
        #pragma unroll
        for (int p = 0; p < 2; ++p) {
            int idx = p * 512 + tid;
            int r = idx >> 3, c4 = idx & 7;
            float4 v = make_float4(0.f, 0.f, 0.f, 0.f);
            if (node0 + r < V_NODES)
                v = *reinterpret_cast<const float4*>(x + (size_t)(node0 + r) * NODE_DIM + kc * 32 + c4 * 4);
            uint4 u = make_uint4(f2tf(v.x), f2tf(v.y), f2tf(v.z), f2tf(v.w));
            *reinterpret_cast<uint4*>(XS + r * 36 + c4 * 4) = u;
        }
        // stage W chunk [256][32], rows interleaved W1/W2
        #pragma unroll
        for (int p = 0; p < 4; ++p) {
            int idx = p * 512 + tid;
            int r = idx >> 3, c4 = idx & 7;
            int j = r >> 1;
            const float* src = (r & 1) ? W2 : W1;
            float4 v = *reinterpret_cast<const float4*>(src + j * NODE_DIM + kc * 32 + c4 * 4);
            uint4 u = make_uint4(f2tf(v.x), f2tf(v.y), f2tf(v.z), f2tf(v.w));
            *reinterpret_cast<uint4*>(WS + r * 36 + c4 * 4) = u;
        }
        __syncthreads();

        const unsigned* XSu = reinterpret_cast<const unsigned*>(XS);
        const unsigned* WSu = reinterpret_cast<const unsigned*>(WS);
        #pragma unroll
        for (int ks = 0; ks < 4; ++ks) {
            unsigned a[2][4];
            const int ro = lane >> 2;
            const int co = ks * 8 + (lane & 3);
            #pragma unroll
            for (int mi = 0; mi < 2; ++mi) {
                int rb = wm * 32 + mi * 16;
                a[mi][0] = XSu[(rb + ro) * 36 + co];
                a[mi][1] = XSu[(rb + ro + 8) * 36 + co];
                a[mi][2] = XSu[(rb + ro) * 36 + co + 4];
                a[mi][3] = XSu[(rb + ro + 8) * 36 + co + 4];
            }
            #pragma unroll
            for (int ni = 0; ni < 8; ++ni) {
                int nr = wn * 64 + ni * 8 + ro;
                unsigned bb0 = WSu[nr * 36 + co];
                unsigned bb1 = WSu[nr * 36 + co + 4];
                mma_tf32(c[0][ni][0], c[0][ni][1], c[0][ni][2], c[0][ni][3],
                         a[0][0], a[0][1], a[0][2], a[0][3], bb0, bb1);
                mma_tf32(c[1][ni][0], c[1][ni][1], c[1][ni][2], c[1][ni][3],
                         a[1][0], a[1][1], a[1][2], a[1][3], bb0, bb1);
            }
        }
    }

    // gids + counts
    if (tid < 128) {
        int node = node0 + tid;
        int g = -1;
        if (node < V_NODES) {
            g = is64 ? (int)reinterpret_cast<const long long*>(n2g)[node]
                     : reinterpret_cast<const int*>(n2g)[node];
            atomicAdd(&g_cnt[g], 1.0f);
        }
        GID[tid] = g;
    }

    // epilogue: gate and stage h into smem.
    // C cols: even -> lin1 value, odd -> lin2 value for same hidden j.
    #pragma unroll
    for (int mi = 0; mi < 2; ++mi) {
        #pragma unroll
        for (int ni = 0; ni < 8; ++ni) {
            int r = wm * 32 + mi * 16 + (lane >> 2);
            int j = wn * 32 + ni * 4 + (lane & 3);
            float bb1 = B1S[j], bb2 = B2S[j];
            HS[r * 132 + j]       = (c[0][ni][0] + bb1) * sigm(c[0][ni][1] + bb2);
            HS[(r + 8) * 132 + j] = (c[0][ni][2] + bb1) * sigm(c[0][ni][3] + bb2);
            // second m-tile (mi indexes c's first dim)
            (void)0;
        }
    }
    // NOTE: loop above handles mi via c[mi]...; rewrite explicitly for both mi:
    #pragma unroll
    for (int ni = 0; ni < 8; ++ni) {
        int r = wm * 32 + 16 + (lane >> 2);
        int j = wn * 32 + ni * 4 + (lane & 3);
        float bb1 = B1S[j], bb2 = B2S[j];
        HS[r * 132 + j]       = (c[1][ni][0] + bb1) * sigm(c[1][ni][1] + bb2);
        HS[(r + 8) * 132 + j] = (c[1][ni][2] + bb1) * sigm(c[1][ni][3] + bb2);
    }
    __syncthreads();

    // vectorized scatter: 128 rows x 32 float4
    #pragma unroll
    for (int idx = tid; idx < 4096; idx += 512) {
        int r = idx >> 5, c4 = idx & 31;
        int g = GID[r];
        if (g >= 0) {
            float4 v = *reinterpret_cast<const float4*>(HS + r * 132 + c4 * 4);
            red4(&g_Z1[(size_t)g * HIDDEN + c4 * 4], v);
        }
    }
}

// ---------------- kernel 3: readout GEMM ----------------
// out[g] = relu( [Z1 | Z1/max(c,1) | gx] @ W3^T + b3 ),  K = 320 in 10 chunks of 32.
// 128 graphs/block, 256 threads = 8 warps, 2(m) x 4(n), warp tile 64(m) x 32(n).
__global__ __launch_bounds__(256, 1)
void k_graphs(const float* __restrict__ gx, const float* __restrict__ W3,
              const float* __restrict__ b3, float* __restrict__ out) {
    __shared__ float ZS[128 * 36];
    __shared__ float WS[128 * 36];
    __shared__ float SS[128];
    __shared__ float B3S[128];

    const int tid = threadIdx.x;
    const int lane = tid & 31;
    const int wid = tid >> 5;
    const int wm = wid >> 2;          // 0..1 -> m base = wm*64
    const int wn = wid & 3;           // 0..3 -> n base = wn*32
    const int g0 = blockIdx.x * 128;

    if (tid < 128) {
        int g = g0 + tid;
        float cn = (g < N_GRAPHS) ? g_cnt[g] : 1.0f;
        SS[tid] = 1.0f / fmaxf(cn, 1.0f);
        B3S[tid] = b3[tid];
    }

    float c[4][4][4];
    #pragma unroll
    for (int mi = 0; mi < 4; ++mi)
        #pragma unroll
        for (int ni = 0; ni < 4; ++ni)
            #pragma unroll
            for (int q = 0; q < 4; ++q) c[mi][ni][q] = 0.f;

    for (int kc = 0; kc < 10; ++kc) {
        __syncthreads();
        // stage Z chunk [128][32]
        #pragma unroll
        for (int p = 0; p < 4; ++p) {
            int idx = p * 256 + tid;
            int r = idx >> 3, c4 = idx & 7;
            int g = g0 + r;
            int kb = kc * 32 + c4 * 4;
            float4 v = make_float4(0.f, 0.f, 0.f, 0.f);
            if (g < N_GRAPHS) {
                if (kc < 4) {
                    v = *reinterpret_cast<const float4*>(g_Z1 + (size_t)g * HIDDEN + kb);
                } else if (kc < 8) {
                    v = *reinterpret_cast<const float4*>(g_Z1 + (size_t)g * HIDDEN + kb - 128);
                    float s = SS[r];
                    v.x *= s; v.y *= s; v.z *= s; v.w *= s;
                } else {
                    v = *reinterpret_cast<const float4*>(gx + (size_t)g * GDIM + kb - 256);
                }
            }
            uint4 u = make_uint4(f2tf(v.x), f2tf(v.y), f2tf(v.z), f2tf(v.w));
            *reinterpret_cast<uint4*>(ZS + r * 36 + c4 * 4) = u;
        }
        // stage W3 chunk [128][32]
        #pragma unroll
        for (int p = 0; p < 4; ++p) {
            int idx = p * 256 + tid;
            int j = idx >> 3, c4 = idx & 7;
            float4 v = *reinterpret_cast<const float4*>(W3 + (size_t)j * 320 + kc * 32 + c4 * 4);
            uint4 u = make_uint4(f2tf(v.x), f2tf(v.y), f2tf(v.z), f2tf(v.w));
            *reinterpret_cast<uint4*>(WS + j * 36 + c4 * 4) = u;
        }
        __syncthreads();

        const unsigned* ZSu = reinterpret_cast<const unsigned*>(ZS);
        const unsigned* WSu = reinterpret_cast<const unsigned*>(WS);
        #pragma unroll
        for (int ks = 0; ks < 4; ++ks) {
            const int ro = lane >> 2;
            const int co = ks * 8 + (lane & 3);
            unsigned a[4][4];
            #pragma unroll
            for (int mi = 0; mi < 4; ++mi) {
                int rb = wm * 64 + mi * 16;
                a[mi][0] = ZSu[(rb + ro) * 36 + co];
                a[mi][1] = ZSu[(rb + ro + 8) * 36 + co];
                a[mi][2] = ZSu[(rb + ro) * 36 + co + 4];
                a[mi][3] = ZSu[(rb + ro + 8) * 36 + co + 4];
            }
            #pragma unroll
            for (int ni = 0; ni < 4; ++ni) {
                int nr = wn * 32 + ni * 8 + ro;
                unsigned bb0 = WSu[nr * 36 + co];
                unsigned bb1 = WSu[nr * 36 + co + 4];
                #pragma unroll
                for (int mi = 0; mi < 4; ++mi)
                    mma_tf32(c[mi][ni][0], c[mi][ni][1], c[mi][ni][2], c[mi][ni][3],
                             a[mi][0], a[mi][1], a[mi][2], a[mi][3], bb0, bb1);
            }
        }
    }

    // epilogue: bias + relu, vectorized float2 stores
    #pragma unroll
    for (int mi = 0; mi < 4; ++mi) {
        #pragma unroll
        for (int ni = 0; ni < 4; ++ni) {
            int r = wm * 64 + mi * 16 + (lane >> 2);
            int n = wn * 32 + ni * 8 + 2 * (lane & 3);
            int g = g0 + r;
            if (g < N_GRAPHS) {
                float2 v;
                v.x = fmaxf(c[mi][ni][0] + B3S[n], 0.f);
                v.y = fmaxf(c[mi][ni][1] + B3S[n + 1], 0.f);
                *reinterpret_cast<float2*>(out + (size_t)g * 128 + n) = v;
            }
            int g2 = g0 + r + 8;
            if (g2 < N_GRAPHS) {
                float2 v;
                v.x = fmaxf(c[mi][ni][2] + B3S[n], 0.f);
                v.y = fmaxf(c[mi][ni][3] + B3S[n + 1], 0.f);
                *reinterpret_cast<float2*>(out + (size_t)g2 * 128 + n) = v;
            }
        }
    }
}

// ---------------- launch ----------------
extern "C" void kernel_launch(void* const* d_in, const int* in_sizes, int n_in,
                              void* d_out, int out_size) {
    const float* x  = (const float*)d_in[0];
    const void*  n2g = d_in[1];
    const float* gx = (const float*)d_in[2];
    const float* W1 = (const float*)d_in[3];
    const float* b1 = (const float*)d_in[4];
    const float* W2 = (const float*)d_in[5];
    const float* b2 = (const float*)d_in[6];
    const float* W3 = (const float*)d_in[7];
    const float* b3 = (const float*)d_in[8];
    float* out = (float*)d_out;

    static bool attr_set = false;
    if (!attr_set) {
        cudaFuncSetAttribute(k_nodes, cudaFuncAttributeMaxDynamicSharedMemorySize, SMEM_NODES_BYTES);
        attr_set = true;
    }

    k_zero<<<2048, 256>>>();
    k_detect<<<1, 1024>>>((const unsigned*)n2g);
    k_nodes<<<(V_NODES + 127) / 128, 512, SMEM_NODES_BYTES>>>(x, n2g, W1, b1, W2, b2);
    k_graphs<<<(N_GRAPHS + 127) / 128, 256>>>(gx, W3, b3, out);
}

// round 4
// speedup vs baseline: 1.1840x; 1.1840x over previous
#include <cuda_runtime.h>
#include <cstdint>

#define V_NODES   1000000
#define N_GRAPHS  50000
#define NODE_DIM  128
#define HIDDEN    128
#define GDIM      64

// ---------------- scratch (no allocation allowed) ----------------
__device__ __align__(256) float g_Z1[(size_t)N_GRAPHS * HIDDEN];   // segment sums
__device__ __align__(256) float g_cnt[N_GRAPHS];                   // segment counts
__device__ int   g_is64;                                           // node2graph dtype flag

// ---------------- helpers ----------------
__device__ __forceinline__ unsigned f2tf(float f) {
    unsigned u;
    asm("cvt.rna.tf32.f32 %0, %1;" : "=r"(u) : "f"(f));
    return u;
}

__device__ __forceinline__ void mma_tf32(float& c0, float& c1, float& c2, float& c3,
                                         unsigned a0, unsigned a1, unsigned a2, unsigned a3,
                                         unsigned b0, unsigned b1) {
    asm volatile(
        "mma.sync.aligned.m16n8k8.row.col.f32.tf32.tf32.f32 "
        "{%0,%1,%2,%3},{%4,%5,%6,%7},{%8,%9},{%0,%1,%2,%3};"
        : "+f"(c0), "+f"(c1), "+f"(c2), "+f"(c3)
        : "r"(a0), "r"(a1), "r"(a2), "r"(a3), "r"(b0), "r"(b1));
}

__device__ __forceinline__ void red4(float* p, float4 v) {
    asm volatile("red.global.add.v4.f32 [%0], {%1,%2,%3,%4};"
                 :: "l"(p), "f"(v.x), "f"(v.y), "f"(v.z), "f"(v.w) : "memory");
}

__device__ __forceinline__ float sigm(float x) { return 1.0f / (1.0f + __expf(-x)); }

// ---------------- kernel 0: zero scratch ----------------
__global__ void k_zero() {
    size_t i = (size_t)blockIdx.x * blockDim.x + threadIdx.x;
    size_t stride = (size_t)gridDim.x * blockDim.x;
    float4* z = reinterpret_cast<float4*>(g_Z1);
    const size_t n4 = (size_t)N_GRAPHS * HIDDEN / 4;
    for (size_t k = i; k < n4; k += stride) z[k] = make_float4(0.f, 0.f, 0.f, 0.f);
    for (size_t k = i; k < N_GRAPHS; k += stride) g_cnt[k] = 0.f;
}

// ---------------- kernel 1: detect int64 vs int32 node2graph ----------------
// If stored little-endian int64 (values < 2^31), every odd 32-bit word is 0.
__global__ void k_detect(const unsigned* __restrict__ n2g_words) {
    __shared__ int nz;
    if (threadIdx.x == 0) nz = 0;
    __syncthreads();
    unsigned w = n2g_words[2 * threadIdx.x + 1];   // idx <= 2047, safe for both layouts
    if (w != 0u) atomicOr(&nz, 1);
    __syncthreads();
    if (threadIdx.x == 0) g_is64 = (nz == 0) ? 1 : 0;
}

// ---------------- kernel 2: node MLP (gated) + segment scatter ----------------
// 128 nodes/block, N=256 (W1/W2 rows interleaved), K=128 in 4 chunks of 32.
// 512 threads = 16 warps, 4(m) x 4(n), warp tile 32(m) x 64(n).
// Double-buffered smem staging, register prefetch, 1 sync per chunk.
#define XS_FL  (128 * 36)             // one X buffer
#define WS_FL  (256 * 36)             // one W buffer
#define NODES_SMEM_FL (2*XS_FL + 2*WS_FL + 128*132 + 128 + 128 + 128)
#define SMEM_NODES_BYTES (NODES_SMEM_FL * 4)

__global__ __launch_bounds__(512, 1)
void k_nodes(const float* __restrict__ x, const void* __restrict__ n2g,
             const float* __restrict__ W1, const float* __restrict__ b1,
             const float* __restrict__ W2, const float* __restrict__ b2) {
    extern __shared__ float smem[];
    float* XS  = smem;                         // [2][128*36]
    float* WS  = smem + 2 * XS_FL;             // [2][256*36]
    float* HS  = smem + 2 * XS_FL + 2 * WS_FL; // [128*132]
    float* B1S = HS + 128 * 132;
    float* B2S = B1S + 128;
    int*   GID = reinterpret_cast<int*>(B2S + 128);

    const int tid = threadIdx.x;
    const int lane = tid & 31;
    const int wid = tid >> 5;
    const int wm = wid >> 2;
    const int wn = wid & 3;
    const int node0 = blockIdx.x * 128;
    const int is64 = g_is64;

    if (tid < 128)       B1S[tid]       = b1[tid];
    else if (tid < 256)  B2S[tid - 128] = b2[tid - 128];

    // graph ids + counts (overlaps with GEMM staging)
    if (tid < 128) {
        int node = node0 + tid;
        int g = -1;
        if (node < V_NODES) {
            g = is64 ? (int)reinterpret_cast<const long long*>(n2g)[node]
                     : reinterpret_cast<const int*>(n2g)[node];
            atomicAdd(&g_cnt[g], 1.0f);
        }
        GID[tid] = g;
    }

    float c[2][8][4];
    #pragma unroll
    for (int mi = 0; mi < 2; ++mi)
        #pragma unroll
        for (int ni = 0; ni < 8; ++ni)
            #pragma unroll
            for (int q = 0; q < 4; ++q) c[mi][ni][q] = 0.f;

    float4 xv[2], wv[4];

    auto load_gmem = [&](int kc) {
        #pragma unroll
        for (int p = 0; p < 2; ++p) {
            int idx = p * 512 + tid;
            int r = idx >> 3, c4 = idx & 7;
            xv[p] = make_float4(0.f, 0.f, 0.f, 0.f);
            if (node0 + r < V_NODES)
                xv[p] = *reinterpret_cast<const float4*>(
                    x + (size_t)(node0 + r) * NODE_DIM + kc * 32 + c4 * 4);
        }
        #pragma unroll
        for (int p = 0; p < 4; ++p) {
            int idx = p * 512 + tid;
            int r = idx >> 3, c4 = idx & 7;
            int j = r >> 1;
            const float* src = (r & 1) ? W2 : W1;
            wv[p] = *reinterpret_cast<const float4*>(src + j * NODE_DIM + kc * 32 + c4 * 4);
        }
    };

    auto store_smem = [&](int buf) {
        float* XSb = XS + buf * XS_FL;
        float* WSb = WS + buf * WS_FL;
        #pragma unroll
        for (int p = 0; p < 2; ++p) {
            int idx = p * 512 + tid;
            int r = idx >> 3, c4 = idx & 7;
            uint4 u = make_uint4(f2tf(xv[p].x), f2tf(xv[p].y), f2tf(xv[p].z), f2tf(xv[p].w));
            *reinterpret_cast<uint4*>(XSb + r * 36 + c4 * 4) = u;
        }
        #pragma unroll
        for (int p = 0; p < 4; ++p) {
            int idx = p * 512 + tid;
            int r = idx >> 3, c4 = idx & 7;
            uint4 u = make_uint4(f2tf(wv[p].x), f2tf(wv[p].y), f2tf(wv[p].z), f2tf(wv[p].w));
            *reinterpret_cast<uint4*>(WSb + r * 36 + c4 * 4) = u;
        }
    };

    load_gmem(0);
    store_smem(0);

    for (int kc = 0; kc < 4; ++kc) {
        __syncthreads();                 // buf[kc&1] writes visible; buf[(kc+1)&1] free
        if (kc < 3) load_gmem(kc + 1);   // prefetch next chunk (latency hidden by mma)

        const unsigned* XSu = reinterpret_cast<const unsigned*>(XS + (kc & 1) * XS_FL);
        const unsigned* WSu = reinterpret_cast<const unsigned*>(WS + (kc & 1) * WS_FL);
        #pragma unroll
        for (int ks = 0; ks < 4; ++ks) {
            unsigned a[2][4];
            const int ro = lane >> 2;
            const int co = ks * 8 + (lane & 3);
            #pragma unroll
            for (int mi = 0; mi < 2; ++mi) {
                int rb = wm * 32 + mi * 16;
                a[mi][0] = XSu[(rb + ro) * 36 + co];
                a[mi][1] = XSu[(rb + ro + 8) * 36 + co];
                a[mi][2] = XSu[(rb + ro) * 36 + co + 4];
                a[mi][3] = XSu[(rb + ro + 8) * 36 + co + 4];
            }
            #pragma unroll
            for (int ni = 0; ni < 8; ++ni) {
                int nr = wn * 64 + ni * 8 + ro;
                unsigned bb0 = WSu[nr * 36 + co];
                unsigned bb1 = WSu[nr * 36 + co + 4];
                mma_tf32(c[0][ni][0], c[0][ni][1], c[0][ni][2], c[0][ni][3],
                         a[0][0], a[0][1], a[0][2], a[0][3], bb0, bb1);
                mma_tf32(c[1][ni][0], c[1][ni][1], c[1][ni][2], c[1][ni][3],
                         a[1][0], a[1][1], a[1][2], a[1][3], bb0, bb1);
            }
        }

        if (kc < 3) store_smem((kc + 1) & 1);
    }

    // epilogue: gate -> HS. C col pairs: even = lin1[j], odd = lin2[j].
    #pragma unroll
    for (int ni = 0; ni < 8; ++ni) {
        int j = wn * 32 + ni * 4 + (lane & 3);
        float bb1 = B1S[j], bb2 = B2S[j];
        int r = wm * 32 + (lane >> 2);
        HS[r * 132 + j]        = (c[0][ni][0] + bb1) * sigm(c[0][ni][1] + bb2);
        HS[(r + 8) * 132 + j]  = (c[0][ni][2] + bb1) * sigm(c[0][ni][3] + bb2);
        HS[(r + 16) * 132 + j] = (c[1][ni][0] + bb1) * sigm(c[1][ni][1] + bb2);
        HS[(r + 24) * 132 + j] = (c[1][ni][2] + bb1) * sigm(c[1][ni][3] + bb2);
    }
    __syncthreads();

    // vectorized scatter: 128 rows x 32 float4
    #pragma unroll
    for (int idx = tid; idx < 4096; idx += 512) {
        int r = idx >> 5, c4 = idx & 31;
        int g = GID[r];
        if (g >= 0) {
            float4 v = *reinterpret_cast<const float4*>(HS + r * 132 + c4 * 4);
            red4(&g_Z1[(size_t)g * HIDDEN + c4 * 4], v);
        }
    }
}

// ---------------- kernel 3: readout GEMM ----------------
// out[g] = relu( [Z1 | Z1/max(c,1) | gx] @ W3^T + b3 ), K = 320 in 10 chunks of 32.
// 128 graphs/block, 256 threads = 8 warps, 2(m) x 4(n), warp tile 64(m) x 32(n).
// Same double-buffer pipeline.
#define GZ_FL (128 * 36)
#define GRAPHS_SMEM_FL (4 * GZ_FL + 128 + 128)
#define SMEM_GRAPHS_BYTES (GRAPHS_SMEM_FL * 4)

__global__ __launch_bounds__(256, 1)
void k_graphs(const float* __restrict__ gx, const float* __restrict__ W3,
              const float* __restrict__ b3, float* __restrict__ out) {
    extern __shared__ float smem[];
    float* ZS  = smem;                 // [2][128*36]
    float* WS  = smem + 2 * GZ_FL;     // [2][128*36]
    float* SS  = smem + 4 * GZ_FL;     // [128]
    float* B3S = SS + 128;             // [128]

    const int tid = threadIdx.x;
    const int lane = tid & 31;
    const int wid = tid >> 5;
    const int wm = wid >> 2;
    const int wn = wid & 3;
    const int g0 = blockIdx.x * 128;

    if (tid < 128) {
        int g = g0 + tid;
        float cn = (g < N_GRAPHS) ? g_cnt[g] : 1.0f;
        SS[tid] = 1.0f / fmaxf(cn, 1.0f);
        B3S[tid] = b3[tid];
    }
    __syncthreads();   // SS needed by Z staging below

    float c[4][4][4];
    #pragma unroll
    for (int mi = 0; mi < 4; ++mi)
        #pragma unroll
        for (int ni = 0; ni < 4; ++ni)
            #pragma unroll
            for (int q = 0; q < 4; ++q) c[mi][ni][q] = 0.f;

    float4 zv[4], wv[4];

    auto load_gmem = [&](int kc) {
        #pragma unroll
        for (int p = 0; p < 4; ++p) {
            int idx = p * 256 + tid;
            int r = idx >> 3, c4 = idx & 7;
            int g = g0 + r;
            int kb = kc * 32 + c4 * 4;
            zv[p] = make_float4(0.f, 0.f, 0.f, 0.f);
            if (g < N_GRAPHS) {
                if (kc < 4) {
                    zv[p] = *reinterpret_cast<const float4*>(g_Z1 + (size_t)g * HIDDEN + kb);
                } else if (kc < 8) {
                    zv[p] = *reinterpret_cast<const float4*>(g_Z1 + (size_t)g * HIDDEN + kb - 128);
                    float s = SS[r];
                    zv[p].x *= s; zv[p].y *= s; zv[p].z *= s; zv[p].w *= s;
                } else {
                    zv[p] = *reinterpret_cast<const float4*>(gx + (size_t)g * GDIM + kb - 256);
                }
            }
        }
        #pragma unroll
        for (int p = 0; p < 4; ++p) {
            int idx = p * 256 + tid;
            int j = idx >> 3, c4 = idx & 7;
            wv[p] = *reinterpret_cast<const float4*>(W3 + (size_t)j * 320 + kc * 32 + c4 * 4);
        }
    };

    auto store_smem = [&](int buf) {
        float* ZSb = ZS + buf * GZ_FL;
        float* WSb = WS + buf * GZ_FL;
        #pragma unroll
        for (int p = 0; p < 4; ++p) {
            int idx = p * 256 + tid;
            int r = idx >> 3, c4 = idx & 7;
            uint4 u = make_uint4(f2tf(zv[p].x), f2tf(zv[p].y), f2tf(zv[p].z), f2tf(zv[p].w));
            *reinterpret_cast<uint4*>(ZSb + r * 36 + c4 * 4) = u;
        }
        #pragma unroll
        for (int p = 0; p < 4; ++p) {
            int idx = p * 256 + tid;
            int j = idx >> 3, c4 = idx & 7;
            uint4 u = make_uint4(f2tf(wv[p].x), f2tf(wv[p].y), f2tf(wv[p].z), f2tf(wv[p].w));
            *reinterpret_cast<uint4*>(WSb + j * 36 + c4 * 4) = u;
        }
    };

    load_gmem(0);
    store_smem(0);

    for (int kc = 0; kc < 10; ++kc) {
        __syncthreads();
        if (kc < 9) load_gmem(kc + 1);

        const unsigned* ZSu = reinterpret_cast<const unsigned*>(ZS + (kc & 1) * GZ_FL);
        const unsigned* WSu = reinterpret_cast<const unsigned*>(WS + (kc & 1) * GZ_FL);
        #pragma unroll
        for (int ks = 0; ks < 4; ++ks) {
            const int ro = lane >> 2;
            const int co = ks * 8 + (lane & 3);
            unsigned a[4][4];
            #pragma unroll
            for (int mi = 0; mi < 4; ++mi) {
                int rb = wm * 64 + mi * 16;
                a[mi][0] = ZSu[(rb + ro) * 36 + co];
                a[mi][1] = ZSu[(rb + ro + 8) * 36 + co];
                a[mi][2] = ZSu[(rb + ro) * 36 + co + 4];
                a[mi][3] = ZSu[(rb + ro + 8) * 36 + co + 4];
            }
            #pragma unroll
            for (int ni = 0; ni < 4; ++ni) {
                int nr = wn * 32 + ni * 8 + ro;
                unsigned bb0 = WSu[nr * 36 + co];
                unsigned bb1 = WSu[nr * 36 + co + 4];
                #pragma unroll
                for (int mi = 0; mi < 4; ++mi)
                    mma_tf32(c[mi][ni][0], c[mi][ni][1], c[mi][ni][2], c[mi][ni][3],
                             a[mi][0], a[mi][1], a[mi][2], a[mi][3], bb0, bb1);
            }
        }

        if (kc < 9) store_smem((kc + 1) & 1);
    }

    // epilogue: bias + relu, vectorized float2 stores
    #pragma unroll
    for (int mi = 0; mi < 4; ++mi) {
        #pragma unroll
        for (int ni = 0; ni < 4; ++ni) {
            int r = wm * 64 + mi * 16 + (lane >> 2);
            int n = wn * 32 + ni * 8 + 2 * (lane & 3);
            int g = g0 + r;
            if (g < N_GRAPHS) {
                float2 v;
                v.x = fmaxf(c[mi][ni][0] + B3S[n], 0.f);
                v.y = fmaxf(c[mi][ni][1] + B3S[n + 1], 0.f);
                *reinterpret_cast<float2*>(out + (size_t)g * 128 + n) = v;
            }
            int g2 = g0 + r + 8;
            if (g2 < N_GRAPHS) {
                float2 v;
                v.x = fmaxf(c[mi][ni][2] + B3S[n], 0.f);
                v.y = fmaxf(c[mi][ni][3] + B3S[n + 1], 0.f);
                *reinterpret_cast<float2*>(out + (size_t)g2 * 128 + n) = v;
            }
        }
    }
}

// ---------------- launch ----------------
extern "C" void kernel_launch(void* const* d_in, const int* in_sizes, int n_in,
                              void* d_out, int out_size) {
    const float* x  = (const float*)d_in[0];
    const void*  n2g = d_in[1];
    const float* gx = (const float*)d_in[2];
    const float* W1 = (const float*)d_in[3];
    const float* b1 = (const float*)d_in[4];
    const float* W2 = (const float*)d_in[5];
    const float* b2 = (const float*)d_in[6];
    const float* W3 = (const float*)d_in[7];
    const float* b3 = (const float*)d_in[8];
    float* out = (float*)d_out;

    static bool attr_set = false;
    if (!attr_set) {
        cudaFuncSetAttribute(k_nodes, cudaFuncAttributeMaxDynamicSharedMemorySize,
                             SMEM_NODES_BYTES);
        cudaFuncSetAttribute(k_graphs, cudaFuncAttributeMaxDynamicSharedMemorySize,
                             SMEM_GRAPHS_BYTES);
        attr_set = true;
    }

    k_zero<<<2048, 256>>>();
    k_detect<<<1, 1024>>>((const unsigned*)n2g);
    k_nodes<<<(V_NODES + 127) / 128, 512, SMEM_NODES_BYTES>>>(x, n2g, W1, b1, W2, b2);
    k_graphs<<<(N_GRAPHS + 127) / 128, 256, SMEM_GRAPHS_BYTES>>>(gx, W3, b3, out);
}

// round 5
// speedup vs baseline: 1.2683x; 1.0712x over previous
#include <cuda_runtime.h>
#include <cstdint>

#define V_NODES   1000000
#define N_GRAPHS  50000
#define NODE_DIM  128
#define HIDDEN    128
#define GDIM      64

// ---------------- scratch ----------------
__device__ __align__(256) float g_Z1[(size_t)N_GRAPHS * HIDDEN];
__device__ __align__(256) float g_cnt[N_GRAPHS];
__device__ int   g_is64;

// ---------------- helpers ----------------
__device__ __forceinline__ unsigned f2tf(float f) {
    unsigned u;
    asm("cvt.rna.tf32.f32 %0, %1;" : "=r"(u) : "f"(f));
    return u;
}

__device__ __forceinline__ void mma_tf32(float& c0, float& c1, float& c2, float& c3,
                                         unsigned a0, unsigned a1, unsigned a2, unsigned a3,
                                         unsigned b0, unsigned b1) {
    asm volatile(
        "mma.sync.aligned.m16n8k8.row.col.f32.tf32.tf32.f32 "
        "{%0,%1,%2,%3},{%4,%5,%6,%7},{%8,%9},{%0,%1,%2,%3};"
        : "+f"(c0), "+f"(c1), "+f"(c2), "+f"(c3)
        : "r"(a0), "r"(a1), "r"(a2), "r"(a3), "r"(b0), "r"(b1));
}

__device__ __forceinline__ void red4(float* p, float4 v) {
    asm volatile("red.global.add.v4.f32 [%0], {%1,%2,%3,%4};"
                 :: "l"(p), "f"(v.x), "f"(v.y), "f"(v.z), "f"(v.w) : "memory");
}

__device__ __forceinline__ float sigm(float x) { return 1.0f / (1.0f + __expf(-x)); }

__device__ __forceinline__ unsigned s2u(const void* p) {
    return (unsigned)__cvta_generic_to_shared(p);
}

__device__ __forceinline__ void cp16(unsigned dst, const void* src, unsigned sz) {
    asm volatile("cp.async.cg.shared.global [%0], [%1], 16, %2;"
                 :: "r"(dst), "l"(src), "r"(sz));
}
__device__ __forceinline__ void cp_commit() {
    asm volatile("cp.async.commit_group;");
}
template <int N>
__device__ __forceinline__ void cp_wait() {
    asm volatile("cp.async.wait_group %0;" :: "n"(N));
}

// ---------------- kernel 0: zero scratch + dtype detect ----------------
__global__ void k_init(const unsigned* __restrict__ n2g_words) {
    if (blockIdx.x == 0) {
        __shared__ int nz;
        if (threadIdx.x == 0) nz = 0;
        __syncthreads();
        unsigned acc = 0;
        #pragma unroll
        for (int q = 0; q < 4; ++q)
            acc |= n2g_words[2 * (threadIdx.x * 4 + q) + 1];   // idx <= 2047
        if (acc != 0u) atomicOr(&nz, 1);
        __syncthreads();
        if (threadIdx.x == 0) g_is64 = (nz == 0) ? 1 : 0;
    }
    size_t i = (size_t)blockIdx.x * blockDim.x + threadIdx.x;
    size_t stride = (size_t)gridDim.x * blockDim.x;
    float4* z = reinterpret_cast<float4*>(g_Z1);
    const size_t n4 = (size_t)N_GRAPHS * HIDDEN / 4;
    for (size_t k = i; k < n4; k += stride) z[k] = make_float4(0.f, 0.f, 0.f, 0.f);
    for (size_t k = i; k < N_GRAPHS; k += stride) g_cnt[k] = 0.f;
}

// ---------------- kernel 1: node MLP (gated) + segment scatter ----------------
// 128 nodes/block, N=256 (W1/W2 interleaved), K=128 in 4 chunks of 32.
// 512 thr = 16 warps, 4(m)x4(n), warp tile 32x64. 3-stage cp.async pipeline,
// one __syncthreads per chunk. tf32 cvt at fragment build.
#define N_STAGE_FL (128*36 + 256*36)     // X + W per stage = 13824 floats
#define SMEM_NODES_FL (3*N_STAGE_FL + 128 + 128 + 128)
#define SMEM_NODES_BYTES (SMEM_NODES_FL * 4)

__global__ __launch_bounds__(512, 1)
void k_nodes(const float* __restrict__ x, const void* __restrict__ n2g,
             const float* __restrict__ W1, const float* __restrict__ b1,
             const float* __restrict__ W2, const float* __restrict__ b2) {
    extern __shared__ float smem[];
    float* B1S = smem + 3 * N_STAGE_FL;
    float* B2S = B1S + 128;
    int*   GID = reinterpret_cast<int*>(B2S + 128);
    float* HS  = smem;                    // reuse stage 0/1 after pipeline drains

    const int tid = threadIdx.x;
    const int lane = tid & 31;
    const int wid = tid >> 5;
    const int wm = wid >> 2;
    const int wn = wid & 3;
    const int node0 = blockIdx.x * 128;
    const int is64 = g_is64;

    auto issue = [&](int kc, int buf) {
        float* XSb = smem + buf * N_STAGE_FL;
        float* WSb = XSb + 128 * 36;
        #pragma unroll
        for (int p = 0; p < 2; ++p) {
            int idx = p * 512 + tid;
            int r = idx >> 3, c4 = idx & 7;
            int node = node0 + r;
            unsigned sz = (node < V_NODES) ? 16u : 0u;
            int nc = (node < V_NODES) ? node : (V_NODES - 1);
            cp16(s2u(XSb + r * 36 + c4 * 4),
                 x + (size_t)nc * NODE_DIM + kc * 32 + c4 * 4, sz);
        }
        #pragma unroll
        for (int p = 0; p < 4; ++p) {
            int idx = p * 512 + tid;
            int r = idx >> 3, c4 = idx & 7;
            int j = r >> 1;
            const float* src = (r & 1) ? W2 : W1;
            cp16(s2u(WSb + r * 36 + c4 * 4),
                 src + j * NODE_DIM + kc * 32 + c4 * 4, 16u);
        }
        cp_commit();
    };

    issue(0, 0);
    issue(1, 1);

    // bias + gid while copies fly
    if (tid < 128)       B1S[tid]       = b1[tid];
    else if (tid < 256)  B2S[tid - 128] = b2[tid - 128];
    if (tid < 128) {
        int node = node0 + tid;
        int g = -1;
        if (node < V_NODES) {
            g = is64 ? (int)reinterpret_cast<const long long*>(n2g)[node]
                     : reinterpret_cast<const int*>(n2g)[node];
            atomicAdd(&g_cnt[g], 1.0f);
        }
        GID[tid] = g;
    }

    float c[2][8][4];
    #pragma unroll
    for (int mi = 0; mi < 2; ++mi)
        #pragma unroll
        for (int ni = 0; ni < 8; ++ni)
            #pragma unroll
            for (int q = 0; q < 4; ++q) c[mi][ni][q] = 0.f;

    const int ro = lane >> 2;
    const int col0 = lane & 3;

    #pragma unroll
    for (int kc = 0; kc < 4; ++kc) {
        if (kc < 3) cp_wait<1>(); else cp_wait<0>();
        __syncthreads();          // chunk kc visible to all; stage (kc+2)%3 free

        const float* XSf = smem + (kc % 3) * N_STAGE_FL;
        const float* WSf = XSf + 128 * 36;
        #pragma unroll
        for (int ks = 0; ks < 4; ++ks) {
            const int co = ks * 8 + col0;
            unsigned a[2][4];
            #pragma unroll
            for (int mi = 0; mi < 2; ++mi) {
                int rb = wm * 32 + mi * 16;
                a[mi][0] = f2tf(XSf[(rb + ro) * 36 + co]);
                a[mi][1] = f2tf(XSf[(rb + ro + 8) * 36 + co]);
                a[mi][2] = f2tf(XSf[(rb + ro) * 36 + co + 4]);
                a[mi][3] = f2tf(XSf[(rb + ro + 8) * 36 + co + 4]);
            }
            #pragma unroll
            for (int ni = 0; ni < 8; ++ni) {
                int nr = wn * 64 + ni * 8 + ro;
                unsigned bb0 = f2tf(WSf[nr * 36 + co]);
                unsigned bb1 = f2tf(WSf[nr * 36 + co + 4]);
                mma_tf32(c[0][ni][0], c[0][ni][1], c[0][ni][2], c[0][ni][3],
                         a[0][0], a[0][1], a[0][2], a[0][3], bb0, bb1);
                mma_tf32(c[1][ni][0], c[1][ni][1], c[1][ni][2], c[1][ni][3],
                         a[1][0], a[1][1], a[1][2], a[1][3], bb0, bb1);
            }
        }

        if (kc + 2 <= 3) issue(kc + 2, (kc + 2) % 3);   // stage safe: its last
                                                        // readers pre-date head sync
    }

    __syncthreads();   // staging dead; HS aliases it

    // epilogue: gate -> HS (col pairs: even=lin1[j], odd=lin2[j])
    #pragma unroll
    for (int ni = 0; ni < 8; ++ni) {
        int j = wn * 32 + ni * 4 + col0;
        float bb1 = B1S[j], bb2 = B2S[j];
        int r = wm * 32 + ro;
        HS[r * 132 + j]        = (c[0][ni][0] + bb1) * sigm(c[0][ni][1] + bb2);
        HS[(r + 8) * 132 + j]  = (c[0][ni][2] + bb1) * sigm(c[0][ni][3] + bb2);
        HS[(r + 16) * 132 + j] = (c[1][ni][0] + bb1) * sigm(c[1][ni][1] + bb2);
        HS[(r + 24) * 132 + j] = (c[1][ni][2] + bb1) * sigm(c[1][ni][3] + bb2);
    }
    __syncthreads();

    // vectorized scatter: 128 rows x 32 float4
    #pragma unroll
    for (int idx = tid; idx < 4096; idx += 512) {
        int r = idx >> 5, c4 = idx & 31;
        int g = GID[r];
        if (g >= 0) {
            float4 v = *reinterpret_cast<const float4*>(HS + r * 132 + c4 * 4);
            red4(&g_Z1[(size_t)g * HIDDEN + c4 * 4], v);
        }
    }
}

// ---------------- kernel 2: readout GEMM ----------------
// out[g] = relu([Z1 | Z1/max(c,1) | gx] @ W3^T + b3), K=320 in 10 chunks of 32.
// 128 graphs/block, 256 thr = 8 warps, 2(m)x4(n), warp tile 64x32.
// 3-stage cp.async, 1/count scaling applied at fragment build. <=128 regs -> 2 CTA/SM.
#define G_STAGE_FL (128*36 + 128*36)    // Z + W3 per stage = 9216 floats
#define SMEM_GRAPHS_FL (3*G_STAGE_FL + 128 + 128)
#define SMEM_GRAPHS_BYTES (SMEM_GRAPHS_FL * 4)

__global__ __launch_bounds__(256, 2)
void k_graphs(const float* __restrict__ gx, const float* __restrict__ W3,
              const float* __restrict__ b3, float* __restrict__ out) {
    extern __shared__ float smem[];
    float* SS  = smem + 3 * G_STAGE_FL;
    float* B3S = SS + 128;

    const int tid = threadIdx.x;
    const int lane = tid & 31;
    const int wid = tid >> 5;
    const int wm = wid >> 2;
    const int wn = wid & 3;
    const int g0 = blockIdx.x * 128;

    auto issue = [&](int kc, int buf) {
        float* ZSb = smem + buf * G_STAGE_FL;
        float* WSb = ZSb + 128 * 36;
        #pragma unroll
        for (int p = 0; p < 4; ++p) {
            int idx = p * 256 + tid;
            int r = idx >> 3, c4 = idx & 7;
            int g = g0 + r;
            unsigned sz = (g < N_GRAPHS) ? 16u : 0u;
            int gc = (g < N_GRAPHS) ? g : (N_GRAPHS - 1);
            const float* src;
            if (kc < 4)      src = g_Z1 + (size_t)gc * HIDDEN + kc * 32 + c4 * 4;
            else if (kc < 8) src = g_Z1 + (size_t)gc * HIDDEN + (kc - 4) * 32 + c4 * 4;
            else             src = gx + (size_t)gc * GDIM + (kc - 8) * 32 + c4 * 4;
            cp16(s2u(ZSb + r * 36 + c4 * 4), src, sz);
        }
        #pragma unroll
        for (int p = 0; p < 4; ++p) {
            int idx = p * 256 + tid;
            int j = idx >> 3, c4 = idx & 7;
            cp16(s2u(WSb + j * 36 + c4 * 4),
                 W3 + (size_t)j * 320 + kc * 32 + c4 * 4, 16u);
        }
        cp_commit();
    };

    issue(0, 0);
    issue(1, 1);

    if (tid < 128) {
        int g = g0 + tid;
        float cn = (g < N_GRAPHS) ? g_cnt[g] : 1.0f;
        SS[tid] = 1.0f / fmaxf(cn, 1.0f);
        B3S[tid] = b3[tid];
    }

    float c[4][4][4];
    #pragma unroll
    for (int mi = 0; mi < 4; ++mi)
        #pragma unroll
        for (int ni = 0; ni < 4; ++ni)
            #pragma unroll
            for (int q = 0; q < 4; ++q) c[mi][ni][q] = 0.f;

    const int ro = lane >> 2;
    const int col0 = lane & 3;

    for (int kc = 0; kc < 10; ++kc) {
        if (kc < 9) cp_wait<1>(); else cp_wait<0>();
        __syncthreads();

        const float* ZSf = smem + (kc % 3) * G_STAGE_FL;
        const float* WSf = ZSf + 128 * 36;
        const bool isZ2 = (kc >= 4) && (kc < 8);

        float s0[4], s1[4];
        #pragma unroll
        for (int mi = 0; mi < 4; ++mi) {
            int rb = wm * 64 + mi * 16;
            s0[mi] = isZ2 ? SS[rb + ro]     : 1.0f;
            s1[mi] = isZ2 ? SS[rb + ro + 8] : 1.0f;
        }

        #pragma unroll
        for (int ks = 0; ks < 4; ++ks) {
            const int co = ks * 8 + col0;
            unsigned a[4][4];
            #pragma unroll
            for (int mi = 0; mi < 4; ++mi) {
                int rb = wm * 64 + mi * 16;
                a[mi][0] = f2tf(ZSf[(rb + ro) * 36 + co]     * s0[mi]);
                a[mi][1] = f2tf(ZSf[(rb + ro + 8) * 36 + co] * s1[mi]);
                a[mi][2] = f2tf(ZSf[(rb + ro) * 36 + co + 4]     * s0[mi]);
                a[mi][3] = f2tf(ZSf[(rb + ro + 8) * 36 + co + 4] * s1[mi]);
            }
            #pragma unroll
            for (int ni = 0; ni < 4; ++ni) {
                int nr = wn * 32 + ni * 8 + ro;
                unsigned bb0 = f2tf(WSf[nr * 36 + co]);
                unsigned bb1 = f2tf(WSf[nr * 36 + co + 4]);
                #pragma unroll
                for (int mi = 0; mi < 4; ++mi)
                    mma_tf32(c[mi][ni][0], c[mi][ni][1], c[mi][ni][2], c[mi][ni][3],
                             a[mi][0], a[mi][1], a[mi][2], a[mi][3], bb0, bb1);
            }
        }

        if (kc + 2 <= 9) issue(kc + 2, (kc + 2) % 3);
    }

    // epilogue: bias + relu
    #pragma unroll
    for (int mi = 0; mi < 4; ++mi) {
        #pragma unroll
        for (int ni = 0; ni < 4; ++ni) {
            int r = wm * 64 + mi * 16 + ro;
            int n = wn * 32 + ni * 8 + 2 * col0;
            int g = g0 + r;
            if (g < N_GRAPHS) {
                float2 v;
                v.x = fmaxf(c[mi][ni][0] + B3S[n], 0.f);
                v.y = fmaxf(c[mi][ni][1] + B3S[n + 1], 0.f);
                *reinterpret_cast<float2*>(out + (size_t)g * 128 + n) = v;
            }
            int g2 = g0 + r + 8;
            if (g2 < N_GRAPHS) {
                float2 v;
                v.x = fmaxf(c[mi][ni][2] + B3S[n], 0.f);
                v.y = fmaxf(c[mi][ni][3] + B3S[n + 1], 0.f);
                *reinterpret_cast<float2*>(out + (size_t)g2 * 128 + n) = v;
            }
        }
    }
}

// ---------------- launch ----------------
extern "C" void kernel_launch(void* const* d_in, const int* in_sizes, int n_in,
                              void* d_out, int out_size) {
    const float* x  = (const float*)d_in[0];
    const void*  n2g = d_in[1];
    const float* gx = (const float*)d_in[2];
    const float* W1 = (const float*)d_in[3];
    const float* b1 = (const float*)d_in[4];
    const float* W2 = (const float*)d_in[5];
    const float* b2 = (const float*)d_in[6];
    const float* W3 = (const float*)d_in[7];
    const float* b3 = (const float*)d_in[8];
    float* out = (float*)d_out;

    static bool attr_set = false;
    if (!attr_set) {
        cudaFuncSetAttribute(k_nodes, cudaFuncAttributeMaxDynamicSharedMemorySize,
                             SMEM_NODES_BYTES);
        cudaFuncSetAttribute(k_graphs, cudaFuncAttributeMaxDynamicSharedMemorySize,
                             SMEM_GRAPHS_BYTES);
        attr_set = true;
    }

    k_init<<<2048, 256>>>((const unsigned*)n2g);
    k_nodes<<<(V_NODES + 127) / 128, 512, SMEM_NODES_BYTES>>>(x, n2g, W1, b1, W2, b2);
    k_graphs<<<(N_GRAPHS + 127) / 128, 256, SMEM_GRAPHS_BYTES>>>(gx, W3, b3, out);
}

// round 6
// speedup vs baseline: 1.3032x; 1.0276x over previous
#include <cuda_runtime.h>
#include <cstdint>

#define V_NODES   1000000
#define N_GRAPHS  50000
#define NODE_DIM  128
#define HIDDEN    128
#define GDIM      64

// ---------------- scratch ----------------
__device__ __align__(256) float    g_Z1[(size_t)N_GRAPHS * HIDDEN];
__device__ __align__(256) float    g_cnt[N_GRAPHS];
__device__ __align__(256) unsigned g_Wtf[256 * NODE_DIM];   // W1/W2 interleaved, tf32 bits
__device__ int g_is64;

// ---------------- helpers ----------------
__device__ __forceinline__ unsigned f2tf(float f) {
    unsigned u;
    asm("cvt.rna.tf32.f32 %0, %1;" : "=r"(u) : "f"(f));
    return u;
}

__device__ __forceinline__ void mma_tf32(float& c0, float& c1, float& c2, float& c3,
                                         unsigned a0, unsigned a1, unsigned a2, unsigned a3,
                                         unsigned b0, unsigned b1) {
    asm volatile(
        "mma.sync.aligned.m16n8k8.row.col.f32.tf32.tf32.f32 "
        "{%0,%1,%2,%3},{%4,%5,%6,%7},{%8,%9},{%0,%1,%2,%3};"
        : "+f"(c0), "+f"(c1), "+f"(c2), "+f"(c3)
        : "r"(a0), "r"(a1), "r"(a2), "r"(a3), "r"(b0), "r"(b1));
}

__device__ __forceinline__ void red4(float* p, float4 v) {
    asm volatile("red.global.add.v4.f32 [%0], {%1,%2,%3,%4};"
                 :: "l"(p), "f"(v.x), "f"(v.y), "f"(v.z), "f"(v.w) : "memory");
}

__device__ __forceinline__ float sigm(float x) { return 1.0f / (1.0f + __expf(-x)); }

__device__ __forceinline__ unsigned s2u(const void* p) {
    return (unsigned)__cvta_generic_to_shared(p);
}

__device__ __forceinline__ void cp16(unsigned dst, const void* src, unsigned sz) {
    asm volatile("cp.async.cg.shared.global [%0], [%1], 16, %2;"
                 :: "r"(dst), "l"(src), "r"(sz));
}
__device__ __forceinline__ void cp_commit() {
    asm volatile("cp.async.commit_group;");
}
template <int N>
__device__ __forceinline__ void cp_wait() {
    asm volatile("cp.async.wait_group %0;" :: "n"(N));
}

// ---------------- kernel 0: zero scratch + dtype detect + W pre-convert ----------------
__global__ void k_init(const unsigned* __restrict__ n2g_words,
                       const float* __restrict__ W1, const float* __restrict__ W2) {
    if (blockIdx.x == 0) {
        __shared__ int nz;
        if (threadIdx.x == 0) nz = 0;
        __syncthreads();
        unsigned acc = 0;
        #pragma unroll
        for (int q = 0; q < 4; ++q)
            acc |= n2g_words[2 * (threadIdx.x * 4 + q) + 1];   // idx <= 2047
        if (acc != 0u) atomicOr(&nz, 1);
        __syncthreads();
        if (threadIdx.x == 0) g_is64 = (nz == 0) ? 1 : 0;
    }
    size_t i = (size_t)blockIdx.x * blockDim.x + threadIdx.x;
    size_t stride = (size_t)gridDim.x * blockDim.x;

    // W interleave + tf32 convert: row 2j = W1[j], row 2j+1 = W2[j]
    for (size_t k = i; k < 256 * NODE_DIM; k += stride) {
        int r = (int)(k >> 7), c = (int)(k & 127);
        const float* src = (r & 1) ? W2 : W1;
        g_Wtf[k] = f2tf(src[(r >> 1) * NODE_DIM + c]);
    }

    float4* z = reinterpret_cast<float4*>(g_Z1);
    const size_t n4 = (size_t)N_GRAPHS * HIDDEN / 4;
    for (size_t k = i; k < n4; k += stride) z[k] = make_float4(0.f, 0.f, 0.f, 0.f);
    for (size_t k = i; k < N_GRAPHS; k += stride) g_cnt[k] = 0.f;
}

// ---------------- kernel 1: node MLP (gated) + segment scatter ----------------
// 128 nodes/block, N=256, K=128 in 4 chunks of 32. 512 thr = 16 warps, 4x4 warp
// grid, warp tile 32x64. W resident in smem (pre-converted tf32, loaded once per
// block). X-only 3-stage cp.async pipeline. HS aliases X stages after drain.
#define WT_FL   (256 * 132)              // resident W, stride 132
#define XSTG_FL (128 * 36)               // one X stage
#define HS_FL   (128 * 132)              // gated output staging (aliases X stages)
#define SMEM_NODES_FL (WT_FL + HS_FL + 128 + 128 + 128)
#define SMEM_NODES_BYTES (SMEM_NODES_FL * 4)

__global__ __launch_bounds__(512, 1)
void k_nodes(const float* __restrict__ x, const void* __restrict__ n2g,
             const float* __restrict__ b1, const float* __restrict__ b2) {
    extern __shared__ float smem[];
    float* WT  = smem;                    // [256*132] tf32 bits
    float* XS  = smem + WT_FL;            // [3][128*36] (lives inside HS region)
    float* HS  = smem + WT_FL;            // [128*132] after pipeline drains
    float* B1S = smem + WT_FL + HS_FL;
    float* B2S = B1S + 128;
    int*   GID = reinterpret_cast<int*>(B2S + 128);

    const int tid = threadIdx.x;
    const int lane = tid & 31;
    const int wid = tid >> 5;
    const int wm = wid >> 2;
    const int wn = wid & 3;
    const int node0 = blockIdx.x * 128;
    const int is64 = g_is64;

    // ---- group 0: resident W copy (pre-converted bits, no cvt needed) ----
    #pragma unroll
    for (int p = 0; p < 16; ++p) {
        int idx = p * 512 + tid;
        int r = idx >> 5, c4 = idx & 31;     // 32 float4 per row
        cp16(s2u(WT + r * 132 + c4 * 4), g_Wtf + r * 128 + c4 * 4, 16u);
    }
    cp_commit();

    auto issueX = [&](int kc, int buf) {
        float* XSb = XS + buf * XSTG_FL;
        #pragma unroll
        for (int p = 0; p < 2; ++p) {
            int idx = p * 512 + tid;
            int r = idx >> 3, c4 = idx & 7;
            int node = node0 + r;
            unsigned sz = (node < V_NODES) ? 16u : 0u;
            int nc = (node < V_NODES) ? node : (V_NODES - 1);
            cp16(s2u(XSb + r * 36 + c4 * 4),
                 x + (size_t)nc * NODE_DIM + kc * 32 + c4 * 4, sz);
        }
        cp_commit();
    };

    issueX(0, 0);   // group 1
    issueX(1, 1);   // group 2

    // bias + gid while copies fly
    if (tid < 128)       B1S[tid]       = b1[tid];
    else if (tid < 256)  B2S[tid - 128] = b2[tid - 128];
    if (tid < 128) {
        int node = node0 + tid;
        int g = -1;
        if (node < V_NODES) {
            g = is64 ? (int)reinterpret_cast<const long long*>(n2g)[node]
                     : reinterpret_cast<const int*>(n2g)[node];
            atomicAdd(&g_cnt[g], 1.0f);
        }
        GID[tid] = g;
    }

    float c[2][8][4];
    #pragma unroll
    for (int mi = 0; mi < 2; ++mi)
        #pragma unroll
        for (int ni = 0; ni < 8; ++ni)
            #pragma unroll
            for (int q = 0; q < 4; ++q) c[mi][ni][q] = 0.f;

    const int ro = lane >> 2;
    const int col0 = lane & 3;
    const unsigned* WTu = reinterpret_cast<const unsigned*>(WT);

    #pragma unroll
    for (int kc = 0; kc < 4; ++kc) {
        if (kc < 3) cp_wait<1>(); else cp_wait<0>();
        __syncthreads();          // chunk kc (and W) visible; stage (kc+2)%3 free

        const float* XSf = XS + (kc % 3) * XSTG_FL;
        #pragma unroll
        for (int ks = 0; ks < 4; ++ks) {
            const int co = ks * 8 + col0;
            unsigned a[2][4];
            #pragma unroll
            for (int mi = 0; mi < 2; ++mi) {
                int rb = wm * 32 + mi * 16;
                a[mi][0] = f2tf(XSf[(rb + ro) * 36 + co]);
                a[mi][1] = f2tf(XSf[(rb + ro + 8) * 36 + co]);
                a[mi][2] = f2tf(XSf[(rb + ro) * 36 + co + 4]);
                a[mi][3] = f2tf(XSf[(rb + ro + 8) * 36 + co + 4]);
            }
            const int wco = kc * 32 + ks * 8 + col0;
            #pragma unroll
            for (int ni = 0; ni < 8; ++ni) {
                int nr = wn * 64 + ni * 8 + ro;
                unsigned bb0 = WTu[nr * 132 + wco];
                unsigned bb1 = WTu[nr * 132 + wco + 4];
                mma_tf32(c[0][ni][0], c[0][ni][1], c[0][ni][2], c[0][ni][3],
                         a[0][0], a[0][1], a[0][2], a[0][3], bb0, bb1);
                mma_tf32(c[1][ni][0], c[1][ni][1], c[1][ni][2], c[1][ni][3],
                         a[1][0], a[1][1], a[1][2], a[1][3], bb0, bb1);
            }
        }

        if (kc + 2 <= 3) issueX(kc + 2, (kc + 2) % 3);
    }

    __syncthreads();   // X staging dead; HS aliases it

    // epilogue: gate -> HS (col pairs: even=lin1[j], odd=lin2[j])
    #pragma unroll
    for (int ni = 0; ni < 8; ++ni) {
        int j = wn * 32 + ni * 4 + col0;
        float bb1 = B1S[j], bb2 = B2S[j];
        int r = wm * 32 + ro;
        HS[r * 132 + j]        = (c[0][ni][0] + bb1) * sigm(c[0][ni][1] + bb2);
        HS[(r + 8) * 132 + j]  = (c[0][ni][2] + bb1) * sigm(c[0][ni][3] + bb2);
        HS[(r + 16) * 132 + j] = (c[1][ni][0] + bb1) * sigm(c[1][ni][1] + bb2);
        HS[(r + 24) * 132 + j] = (c[1][ni][2] + bb1) * sigm(c[1][ni][3] + bb2);
    }
    __syncthreads();

    // vectorized scatter: 128 rows x 32 float4 (one 16B LTS red op each)
    #pragma unroll
    for (int idx = tid; idx < 4096; idx += 512) {
        int r = idx >> 5, c4 = idx & 31;
        int g = GID[r];
        if (g >= 0) {
            float4 v = *reinterpret_cast<const float4*>(HS + r * 132 + c4 * 4);
            red4(&g_Z1[(size_t)g * HIDDEN + c4 * 4], v);
        }
    }
}

// ---------------- kernel 2: readout GEMM ----------------
// out[g] = relu([Z1 | Z1/max(c,1) | gx] @ W3^T + b3), K=320 in 10 chunks of 32.
// 128 graphs/block, 256 thr = 8 warps, 2x4, warp tile 64x32. 3-stage cp.async.
#define G_STAGE_FL (128*36 + 128*36)
#define SMEM_GRAPHS_FL (3*G_STAGE_FL + 128 + 128)
#define SMEM_GRAPHS_BYTES (SMEM_GRAPHS_FL * 4)

__global__ __launch_bounds__(256, 2)
void k_graphs(const float* __restrict__ gx, const float* __restrict__ W3,
              const float* __restrict__ b3, float* __restrict__ out) {
    extern __shared__ float smem[];
    float* SS  = smem + 3 * G_STAGE_FL;
    float* B3S = SS + 128;

    const int tid = threadIdx.x;
    const int lane = tid & 31;
    const int wid = tid >> 5;
    const int wm = wid >> 2;
    const int wn = wid & 3;
    const int g0 = blockIdx.x * 128;

    auto issue = [&](int kc, int buf) {
        float* ZSb = smem + buf * G_STAGE_FL;
        float* WSb = ZSb + 128 * 36;
        #pragma unroll
        for (int p = 0; p < 4; ++p) {
            int idx = p * 256 + tid;
            int r = idx >> 3, c4 = idx & 7;
            int g = g0 + r;
            unsigned sz = (g < N_GRAPHS) ? 16u : 0u;
            int gc = (g < N_GRAPHS) ? g : (N_GRAPHS - 1);
            const float* src;
            if (kc < 4)      src = g_Z1 + (size_t)gc * HIDDEN + kc * 32 + c4 * 4;
            else if (kc < 8) src = g_Z1 + (size_t)gc * HIDDEN + (kc - 4) * 32 + c4 * 4;
            else             src = gx + (size_t)gc * GDIM + (kc - 8) * 32 + c4 * 4;
            cp16(s2u(ZSb + r * 36 + c4 * 4), src, sz);
        }
        #pragma unroll
        for (int p = 0; p < 4; ++p) {
            int idx = p * 256 + tid;
            int j = idx >> 3, c4 = idx & 7;
            cp16(s2u(WSb + j * 36 + c4 * 4),
                 W3 + (size_t)j * 320 + kc * 32 + c4 * 4, 16u);
        }
        cp_commit();
    };

    issue(0, 0);
    issue(1, 1);

    if (tid < 128) {
        int g = g0 + tid;
        float cn = (g < N_GRAPHS) ? g_cnt[g] : 1.0f;
        SS[tid] = 1.0f / fmaxf(cn, 1.0f);
        B3S[tid] = b3[tid];
    }

    float c[4][4][4];
    #pragma unroll
    for (int mi = 0; mi < 4; ++mi)
        #pragma unroll
        for (int ni = 0; ni < 4; ++ni)
            #pragma unroll
            for (int q = 0; q < 4; ++q) c[mi][ni][q] = 0.f;

    const int ro = lane >> 2;
    const int col0 = lane & 3;

    for (int kc = 0; kc < 10; ++kc) {
        if (kc < 9) cp_wait<1>(); else cp_wait<0>();
        __syncthreads();

        const float* ZSf = smem + (kc % 3) * G_STAGE_FL;
        const float* WSf = ZSf + 128 * 36;
        const bool isZ2 = (kc >= 4) && (kc < 8);

        float s0[4], s1[4];
        #pragma unroll
        for (int mi = 0; mi < 4; ++mi) {
            int rb = wm * 64 + mi * 16;
            s0[mi] = isZ2 ? SS[rb + ro]     : 1.0f;
            s1[mi] = isZ2 ? SS[rb + ro + 8] : 1.0f;
        }

        #pragma unroll
        for (int ks = 0; ks < 4; ++ks) {
            const int co = ks * 8 + col0;
            unsigned a[4][4];
            #pragma unroll
            for (int mi = 0; mi < 4; ++mi) {
                int rb = wm * 64 + mi * 16;
                a[mi][0] = f2tf(ZSf[(rb + ro) * 36 + co]     * s0[mi]);
                a[mi][1] = f2tf(ZSf[(rb + ro + 8) * 36 + co] * s1[mi]);
                a[mi][2] = f2tf(ZSf[(rb + ro) * 36 + co + 4]     * s0[mi]);
                a[mi][3] = f2tf(ZSf[(rb + ro + 8) * 36 + co + 4] * s1[mi]);
            }
            #pragma unroll
            for (int ni = 0; ni < 4; ++ni) {
                int nr = wn * 32 + ni * 8 + ro;
                unsigned bb0 = f2tf(WSf[nr * 36 + co]);
                unsigned bb1 = f2tf(WSf[nr * 36 + co + 4]);
                #pragma unroll
                for (int mi = 0; mi < 4; ++mi)
                    mma_tf32(c[mi][ni][0], c[mi][ni][1], c[mi][ni][2], c[mi][ni][3],
                             a[mi][0], a[mi][1], a[mi][2], a[mi][3], bb0, bb1);
            }
        }

        if (kc + 2 <= 9) issue(kc + 2, (kc + 2) % 3);
    }

    // epilogue: bias + relu
    #pragma unroll
    for (int mi = 0; mi < 4; ++mi) {
        #pragma unroll
        for (int ni = 0; ni < 4; ++ni) {
            int r = wm * 64 + mi * 16 + ro;
            int n = wn * 32 + ni * 8 + 2 * col0;
            int g = g0 + r;
            if (g < N_GRAPHS) {
                float2 v;
                v.x = fmaxf(c[mi][ni][0] + B3S[n], 0.f);
                v.y = fmaxf(c[mi][ni][1] + B3S[n + 1], 0.f);
                *reinterpret_cast<float2*>(out + (size_t)g * 128 + n) = v;
            }
            int g2 = g0 + r + 8;
            if (g2 < N_GRAPHS) {
                float2 v;
                v.x = fmaxf(c[mi][ni][2] + B3S[n], 0.f);
                v.y = fmaxf(c[mi][ni][3] + B3S[n + 1], 0.f);
                *reinterpret_cast<float2*>(out + (size_t)g2 * 128 + n) = v;
            }
        }
    }
}

// ---------------- launch ----------------
extern "C" void kernel_launch(void* const* d_in, const int* in_sizes, int n_in,
                              void* d_out, int out_size) {
    const float* x  = (const float*)d_in[0];
    const void*  n2g = d_in[1];
    const float* gx = (const float*)d_in[2];
    const float* W1 = (const float*)d_in[3];
    const float* b1 = (const float*)d_in[4];
    const float* W2 = (const float*)d_in[5];
    const float* b2 = (const float*)d_in[6];
    const float* W3 = (const float*)d_in[7];
    const float* b3 = (const float*)d_in[8];
    float* out = (float*)d_out;

    static bool attr_set = false;
    if (!attr_set) {
        cudaFuncSetAttribute(k_nodes, cudaFuncAttributeMaxDynamicSharedMemorySize,
                             SMEM_NODES_BYTES);
        cudaFuncSetAttribute(k_graphs, cudaFuncAttributeMaxDynamicSharedMemorySize,
                             SMEM_GRAPHS_BYTES);
        attr_set = true;
    }

    k_init<<<2048, 256>>>((const unsigned*)n2g, W1, W2);
    k_nodes<<<(V_NODES + 127) / 128, 512, SMEM_NODES_BYTES>>>(x, n2g, b1, b2);
    k_graphs<<<(N_GRAPHS + 127) / 128, 256, SMEM_GRAPHS_BYTES>>>(gx, W3, b3, out);
}